// round 1
// baseline (speedup 1.0000x reference)
#include <cuda_runtime.h>
#include <math.h>

#define NSTEPS  60
#define BATCH_N 65536
#define H       128
#define NROWS   129          // spot intervals per step (<=128 knots + 1)
#define RSTRIDE 129          // padded row stride in float2 units (bank-friendly)

// Per-step tables: for interval i, pre2_j(spot) = alpha*spot + beta  (beta includes b2)
__device__ float2 g_table[NSTEPS][NROWS * RSTRIDE];   // ~8 MB static scratch
__device__ float  g_knots[NSTEPS][H];                 // sorted knots, FLT_MAX padded

// ---------------------------------------------------------------------------
// Precompute: for each step t, build sorted knots and incremental (alpha,beta)
// tables. 60 blocks x 128 threads; thread = k for setup/sort, = j for sweep.
// ---------------------------------------------------------------------------
__global__ void precompute_kernel(const float* __restrict__ W1,
                                  const float* __restrict__ b1,
                                  const float* __restrict__ W2,
                                  const float* __restrict__ b2)
{
    __shared__ float sa[H], sc[H];
    __shared__ float skey[H];
    __shared__ int   sidx[H];
    __shared__ unsigned char sact[H];

    const int s   = blockIdx.x;
    const int tid = threadIdx.x;          // 0..127
    const float t = (float)s * (float)(1.0 / 12.0);

    // h1_k(spot) = relu(a*spot + c),  a = W1[0,k], c = t*W1[1,k] + b1[k]
    float a = W1[tid];
    float c = fmaf(t, W1[H + tid], b1[tid]);
    sa[tid] = a;
    sc[tid] = c;

    // active as spot -> 0+ :  c > 0  (tie c==0: active iff a>0)
    sact[tid] = ((c > 0.0f) || (c == 0.0f && a > 0.0f)) ? 1 : 0;

    // knot (activation boundary) only matters if thr > 0 and finite
    float key = 3.0e38f;
    int   idx = -1;
    if (a != 0.0f) {
        float thr = -c / a;
        if (thr > 0.0f && isfinite(thr)) { key = thr; idx = tid; }
    }
    skey[tid] = key;
    sidx[tid] = idx;
    __syncthreads();

    // odd-even transposition sort of (key, idx), 128 phases
    for (int ph = 0; ph < H; ++ph) {
        int i = tid;
        if ((((i ^ ph) & 1) == 0) && (i + 1 < H)) {
            float k1 = skey[i], k2 = skey[i + 1];
            if (k2 < k1) {
                skey[i] = k2; skey[i + 1] = k1;
                int p = sidx[i]; sidx[i] = sidx[i + 1]; sidx[i + 1] = p;
            }
        }
        __syncthreads();
    }

    g_knots[s][tid] = skey[tid];

    // sweep: thread owns output column j
    const int j = tid;
    float alpha = 0.0f;
    float beta  = b2[j];
    #pragma unroll 4
    for (int k = 0; k < H; ++k) {
        if (sact[k]) {                       // uniform branch (smem broadcast)
            float w = W2[k * H + j];
            alpha = fmaf(sa[k], w, alpha);
            beta  = fmaf(sc[k], w, beta);
        }
    }
    g_table[s][0 * RSTRIDE + j] = make_float2(alpha, beta);

    for (int i = 0; i < H; ++i) {
        int k = sidx[i];
        if (k >= 0) {
            float ak = sa[k];
            float sg = (ak > 0.0f) ? 1.0f : -1.0f;  // a>0: activate going up; a<0: deactivate
            float w  = W2[k * H + j];
            alpha = fmaf(sg * ak,    w, alpha);
            beta  = fmaf(sg * sc[k], w, beta);
        }
        g_table[s][(i + 1) * RSTRIDE + j] = make_float2(alpha, beta);
    }
}

// ---------------------------------------------------------------------------
// Main: one thread per path. Per step: stage the 133KB table to SMEM, binary
// search the path's interval, evaluate out = sum_j relu(a*s+b)*W3_j + b3,
// then the analytic PnL update (mirrors reference op order / constants).
// ---------------------------------------------------------------------------
__global__ void __launch_bounds__(512, 1)
pnl_kernel(const float* __restrict__ spots,
           const float* __restrict__ W3,
           const float* __restrict__ b3,
           float* __restrict__ out)
{
    extern __shared__ float smem[];
    float2* stab   = (float2*)smem;                       // NROWS*RSTRIDE float2
    float*  sknots = smem + 2 * NROWS * RSTRIDE;          // H floats
    float*  sW3    = sknots + H;                          // H floats

    const int tid = threadIdx.x;
    const int p   = blockIdx.x * 512 + tid;               // 128 blocks * 512 = 65536

    if (tid < H) sW3[tid] = W3[tid];
    const float b3v = b3[0];

    float pnl  = 0.0f;
    float spot = spots[p];

    for (int s = 0; s < NSTEPS; ++s) {
        __syncthreads();
        if (tid < H) sknots[tid] = g_knots[s][tid];
        {
            const float2* src = g_table[s];
            #pragma unroll 4
            for (int idx = tid; idx < NROWS * RSTRIDE; idx += 512)
                stab[idx] = src[idx];
        }
        __syncthreads();

        const float spot_next = spots[(s + 1) * BATCH_N + p];

        // lower_bound: count of knots < spot  -> interval row index in [0,128]
        int lo = 0, hi = H;
        while (lo < hi) {
            int mid = (lo + hi) >> 1;
            if (sknots[mid] < spot) lo = mid + 1; else hi = mid;
        }
        const float2* row = stab + lo * RSTRIDE;

        float acc = b3v;
        #pragma unroll 8
        for (int j = 0; j < H; ++j) {
            float2 ab  = row[j];
            float  pre = fmaf(ab.x, spot, ab.y);
            pre = fmaxf(pre, 0.0f);
            acc = fmaf(pre, sW3[j], acc);
        }

        const float t = (float)s * (float)(1.0 / 12.0);

        float delta = -(acc * acc);
        delta = delta * fminf(expf(-0.01f * delta), 1.0f);          // identity, kept for fidelity
        delta = delta * ((1.0f - expf(-0.01f * (5.0f - t))) * 100.0f);

        const float account = 100.0f * spot * expf(-0.0196f * t);
        const float elam    = expf(-0.01f * t);
        const float fee     = ((float)(0.0196 / 12.0) * account) * elam;
        const float payout  = ((float)(0.01 / 12.0) * fmaxf(100.0f - account, 0.0f)) * elam;

        pnl  = pnl + (fee - payout) + delta * (spot_next - spot);
        spot = spot_next;
    }

    out[p] = pnl;
}

// ---------------------------------------------------------------------------
extern "C" void kernel_launch(void* const* d_in, const int* in_sizes, int n_in,
                              void* d_out, int out_size)
{
    const float* spots = (const float*)d_in[0];
    const float* W1    = (const float*)d_in[1];
    const float* b1    = (const float*)d_in[2];
    const float* W2    = (const float*)d_in[3];
    const float* b2    = (const float*)d_in[4];
    const float* W3    = (const float*)d_in[5];
    const float* b3    = (const float*)d_in[6];
    float*       out   = (float*)d_out;

    const int smem_bytes = (2 * NROWS * RSTRIDE + 2 * H) * (int)sizeof(float); // ~134 KB
    cudaFuncSetAttribute(pnl_kernel,
                         cudaFuncAttributeMaxDynamicSharedMemorySize, smem_bytes);

    precompute_kernel<<<NSTEPS, H>>>(W1, b1, W2, b2);
    pnl_kernel<<<BATCH_N / 512, 512, smem_bytes>>>(spots, W3, b3, out);
}

// round 9
// speedup vs baseline: 1.7693x; 1.7693x over previous
#include <cuda_runtime.h>
#include <math.h>

#define NSTEPS   60
#define BATCH_N  65536
#define H        128
#define CAP_G    16704          // worst-case segments per step, never exceeded
#define NCH      4              // step chunks
#define SPC      15             // steps per chunk
#define SMEM_CAP 14000          // staged segments per CTA (12 B each)
#define NB       512            // buckets per step for search seeding

// Compact per-step piecewise-linear representation of out(spot):
//   segment e valid on [kn[e-1], kn[e])  (kn[-1]=0, kn[cnt-1]=inf implied)
//   out(spot) = gh[e].x * spot + gh[e].y
__device__ float  g_ckn[NSTEPS][CAP_G];
__device__ float2 g_cgh[NSTEPS][CAP_G];
__device__ int    g_cnt[NSTEPS];
__device__ float4 g_coef[NSTEPS];      // (F, A, P, D) per-step analytic constants
__device__ float  g_part[NCH][BATCH_N];

// ---------------------------------------------------------------------------
// Build: one block per step. Sort layer-1 knots, sweep intervals left->right
// maintaining per-j (alpha,beta) of pre2_j; per interval reduce base (G,H),
// find layer-2 zero crossings inside the interval, emit compact segments.
// ---------------------------------------------------------------------------
__global__ void build_kernel(const float* __restrict__ W1,
                             const float* __restrict__ b1,
                             const float* __restrict__ W2,
                             const float* __restrict__ b2,
                             const float* __restrict__ W3,
                             const float* __restrict__ b3)
{
    __shared__ float  sa[H], sc[H], skey[H];
    __shared__ int    sidx[H];
    __shared__ float  ck[H], cdg[H], cdh[H];
    __shared__ float2 sred[4];
    __shared__ int    s_m, s_n;

    const int s = blockIdx.x;
    const int j = threadIdx.x;               // 0..127
    const float t = (float)s * (float)(1.0 / 12.0);

    if (j == 0) {
        float elam = expf(-0.01f * t);
        float A = 100.0f * expf(-0.0196f * t);
        float F = (float)(0.0196 / 12.0) * A * elam;
        float P = (float)(0.01 / 12.0) * elam;
        float D = (1.0f - expf(-0.01f * (5.0f - t))) * 100.0f;
        g_coef[s] = make_float4(F, A, P, D);
    }

    // layer-1 unit j: h1_j(spot) = relu(a*spot + c)
    float a = W1[j];
    float c = fmaf(t, W1[H + j], b1[j]);
    sa[j] = a; sc[j] = c;
    const float w3 = W3[j];
    const float b3v = b3[0];

    float key = 3.0e38f; int idx = -1;
    if (a != 0.0f) {
        float thr = -c / a;
        if (thr > 0.0f && isfinite(thr)) { key = thr; idx = j; }
    }
    skey[j] = key; sidx[j] = idx;
    __syncthreads();

    // odd-even sort of (key, idx)
    for (int ph = 0; ph < H; ++ph) {
        int i = j;
        if ((((i ^ ph) & 1) == 0) && (i + 1 < H)) {
            float k1 = skey[i], k2 = skey[i + 1];
            if (k2 < k1) {
                skey[i] = k2; skey[i + 1] = k1;
                int p = sidx[i]; sidx[i] = sidx[i + 1]; sidx[i + 1] = p;
            }
        }
        __syncthreads();
    }

    // alpha,beta for interval 0 (spot -> 0+)
    float alpha = 0.0f, beta = b2[j];
    #pragma unroll 4
    for (int k = 0; k < H; ++k) {
        float ck1 = sc[k], ak = sa[k];
        if (ck1 > 0.0f || (ck1 == 0.0f && ak > 0.0f)) {
            float w = W2[k * H + j];
            alpha = fmaf(ak,  w, alpha);
            beta  = fmaf(ck1, w, beta);
        }
    }
    if (j == 0) s_n = 0;
    __syncthreads();

    const int lane = j & 31, warp = j >> 5;

    for (int i = 0; i <= H; ++i) {
        float Klo = (i == 0) ? 0.0f : skey[i - 1];
        if (Klo >= 1.0e37f) break;                    // uniform -> all break
        if (i > 0) {
            int k = sidx[i - 1];
            float ak = sa[k];
            float sg = (ak > 0.0f) ? 1.0f : -1.0f;
            float w  = W2[k * H + j];
            alpha = fmaf(sg * ak,    w, alpha);
            beta  = fmaf(sg * sc[k], w, beta);
        }
        float Khi = (i < H) ? skey[i] : 3.0e38f;

        float pre = fmaf(alpha, Klo, beta);
        bool act = (pre > 0.0f) || (pre == 0.0f && alpha > 0.0f);
        float gv = act ? alpha * w3 : 0.0f;
        float hv = act ? beta  * w3 : 0.0f;
        #pragma unroll
        for (int o = 16; o > 0; o >>= 1) {
            gv += __shfl_down_sync(0xffffffffu, gv, o);
            hv += __shfl_down_sync(0xffffffffu, hv, o);
        }
        if (lane == 0) sred[warp] = make_float2(gv, hv);
        if (j == 0) s_m = 0;
        __syncthreads();

        if (alpha != 0.0f) {
            float y = -beta / alpha;
            if (y > Klo && y < Khi && isfinite(y)) {
                int q = atomicAdd(&s_m, 1);
                float sg2 = (alpha > 0.0f) ? 1.0f : -1.0f;
                ck[q]  = y;
                cdg[q] = sg2 * alpha * w3;
                cdh[q] = sg2 * beta  * w3;
            }
        }
        __syncthreads();

        if (j == 0) {
            float2 r0 = sred[0], r1 = sred[1], r2 = sred[2], r3 = sred[3];
            float G = r0.x + r1.x + r2.x + r3.x;
            float Hh = (r0.y + r1.y + r2.y + r3.y) + b3v;
            int n = s_n;
            if (i == 0) { g_cgh[s][0] = make_float2(G, Hh); n = 1; }
            else        { g_ckn[s][n - 1] = Klo; g_cgh[s][n] = make_float2(G, Hh); n++; }

            int m = s_m;
            for (int u = 1; u < m; ++u) {     // insertion sort (m is tiny)
                float kv = ck[u], dg = cdg[u], dh = cdh[u];
                int v = u - 1;
                while (v >= 0 && ck[v] > kv) {
                    ck[v + 1] = ck[v]; cdg[v + 1] = cdg[v]; cdh[v + 1] = cdh[v]; --v;
                }
                ck[v + 1] = kv; cdg[v + 1] = dg; cdh[v + 1] = dh;
            }
            for (int u = 0; u < m; ++u) {
                G += cdg[u]; Hh += cdh[u];
                g_ckn[s][n - 1] = ck[u];
                g_cgh[s][n] = make_float2(G, Hh);
                n++;
            }
            s_n = n;
        }
        __syncthreads();
    }
    if (j == 0) g_cnt[s] = s_n;
}

// ---------------------------------------------------------------------------
// Eval: grid (128 path-blocks, NCH chunks) x 512 threads. Stage this chunk's
// compact tables into SMEM, build a per-step uniform bucket seed index, then
// per path-step: bucket seed + exact local scan + 1 fma + folded pnl update.
// Hot loop: no transcendentals (fmin(exp(-0.01*delta),1)==1 since delta<=0).
// ---------------------------------------------------------------------------
__global__ void __launch_bounds__(512, 1)
eval_kernel(const float* __restrict__ spots)
{
    extern __shared__ char smem_raw[];
    float2*         sgh    = (float2*)smem_raw;            // [SMEM_CAP]
    float*          skn    = (float*)(sgh + SMEM_CAP);     // [SMEM_CAP]
    unsigned short* sstart = (unsigned short*)(skn + SMEM_CAP); // [SPC*NB]

    __shared__ int    soff[SPC];
    __shared__ int    scnt[SPC];
    __shared__ float  sblo[SPC], sbinv[SPC], sbw[SPC];
    __shared__ float4 scoef[SPC];

    const int tid = threadIdx.x;
    const int c   = blockIdx.y;
    const int s0  = c * SPC;

    if (tid == 0) {
        int run = 0;
        for (int i = 0; i < SPC; ++i) {
            int cnt = g_cnt[s0 + i];
            scnt[i] = cnt;
            if (run + cnt <= SMEM_CAP) { soff[i] = run; run += cnt; }
            else                       { soff[i] = -1; }   // fallback: global
        }
    }
    if (tid >= 32 && tid < 32 + SPC) scoef[tid - 32] = g_coef[s0 + tid - 32];
    __syncthreads();

    // stage tables
    for (int i = 0; i < SPC; ++i) {
        int off = soff[i], cnt = scnt[i];
        if (off < 0) continue;
        const float*  kn = g_ckn[s0 + i];
        const float2* gh = g_cgh[s0 + i];
        for (int q = tid; q < cnt; q += 512) {
            sgh[off + q] = gh[q];
            if (q < cnt - 1) skn[off + q] = kn[q];
        }
    }
    __syncthreads();

    // per-step bucket params (knot range)
    if (tid < SPC) {
        int i = tid, off = soff[i], cnt = scnt[i];
        float lo = 0.0f, invw = 0.0f, w = 0.0f;
        if (off >= 0 && cnt > 1) {
            lo = skn[off];
            float hi = skn[off + cnt - 2];
            if (hi > lo) { w = (hi - lo) * (1.0f / NB); invw = (float)NB / (hi - lo); }
        }
        sblo[i] = lo; sbinv[i] = invw; sbw[i] = w;
    }
    __syncthreads();

    // bucket seeds: sstart[i*NB+q] = lower_bound(kn_i, bucket_left)
    for (int wv = tid; wv < SPC * NB; wv += 512) {
        int i = wv >> 9, q = wv & (NB - 1);
        int off = soff[i], cnt = scnt[i];
        if (off < 0) { continue; }
        float left = fmaf((float)q, sbw[i], sblo[i]);
        const float* kn = skn + off;
        int lo = 0, hi = cnt - 1;
        while (lo < hi) {
            int mid = (lo + hi) >> 1;
            if (kn[mid] < left) lo = mid + 1; else hi = mid;
        }
        sstart[wv] = (unsigned short)lo;
    }
    __syncthreads();

    const int p = blockIdx.x * 512 + tid;
    float spot = spots[s0 * BATCH_N + p];
    float pnl  = 0.0f;

    for (int i = 0; i < SPC; ++i) {
        const int s = s0 + i;
        const float spot_next = spots[(s + 1) * BATCH_N + p];
        const int cnt = scnt[i], off = soff[i];
        float2 GH;

        if (off >= 0) {
            const float* kn = skn + off;
            int b = (int)((spot - sblo[i]) * sbinv[i]);
            b = min(max(b, 0), NB - 1);
            int idx = sstart[(i << 9) + b];
            const int lim = cnt - 1;
            // exact lower_bound from any seed (bucket is only a hint)
            while (idx > 0 && kn[idx - 1] >= spot) --idx;
            while (idx < lim && kn[idx] < spot) ++idx;
            GH = sgh[off + idx];
        } else {
            const float*  kn = g_ckn[s];
            const float2* gh = g_cgh[s];
            int lo = 0, hi = cnt - 1;
            while (lo < hi) {
                int mid = (lo + hi) >> 1;
                if (kn[mid] < spot) lo = mid + 1; else hi = mid;
            }
            GH = gh[lo];
        }

        float outv = fmaf(GH.x, spot, GH.y);

        const float4 cf = scoef[i];                   // (F, A, P, D)
        float delta  = -(outv * outv) * cf.w;
        float fee    = cf.x * spot;
        float payout = cf.z * fmaxf(fmaf(-cf.y, spot, 100.0f), 0.0f);

        pnl  = pnl + (fee - payout) + delta * (spot_next - spot);
        spot = spot_next;
    }
    g_part[c][p] = pnl;
}

__global__ void reduce_kernel(float* __restrict__ out)
{
    const int p = blockIdx.x * 256 + threadIdx.x;
    out[p] = (g_part[0][p] + g_part[1][p]) + (g_part[2][p] + g_part[3][p]);
}

// ---------------------------------------------------------------------------
extern "C" void kernel_launch(void* const* d_in, const int* in_sizes, int n_in,
                              void* d_out, int out_size)
{
    const float* spots = (const float*)d_in[0];
    const float* W1    = (const float*)d_in[1];
    const float* b1    = (const float*)d_in[2];
    const float* W2    = (const float*)d_in[3];
    const float* b2    = (const float*)d_in[4];
    const float* W3    = (const float*)d_in[5];
    const float* b3    = (const float*)d_in[6];
    float*       out   = (float*)d_out;

    const int smem_bytes = SMEM_CAP * 12 + SPC * NB * 2;   // ~183 KB
    cudaFuncSetAttribute(eval_kernel,
                         cudaFuncAttributeMaxDynamicSharedMemorySize, smem_bytes);

    build_kernel<<<NSTEPS, H>>>(W1, b1, W2, b2, W3, b3);
    eval_kernel<<<dim3(BATCH_N / 512, NCH), 512, smem_bytes>>>(spots);
    reduce_kernel<<<BATCH_N / 256, 256>>>(out);
}

// round 12
// speedup vs baseline: 2.1467x; 1.2134x over previous
#include <cuda_runtime.h>
#include <math.h>

#define NSTEPS   60
#define BATCH_N  65536
#define H        128
#define CAP_G    16704          // worst-case segments per step
#define NCH      4              // step chunks (eval)
#define SPC      15             // steps per chunk
#define SMEM_CAP 14000          // staged segments per CTA (12 B each)
#define NB       512            // buckets per step for search seeding
#define CHUNK    33             // intervals per build warp
#define CAP_W    (CHUNK * (H + 1))   // 4257 worst-case segments per warp chunk

// Compact per-step piecewise-linear representation of out(spot):
//   segment e valid on [kn[e-1], kn[e])  (kn[-1]=0, kn[cnt-1]=inf implied)
__device__ float  g_ckn[NSTEPS][CAP_G];
__device__ float2 g_cgh[NSTEPS][CAP_G];
__device__ int    g_cnt[NSTEPS];
__device__ float4 g_coef[NSTEPS];            // (F, A, P, D)
__device__ float2 g_brange[NSTEPS];          // (blo, binv)
__device__ unsigned short g_seed[NSTEPS][NB];
__device__ float  g_part[NCH][BATCH_N];

// ---------------------------------------------------------------------------
// Build: one block per step, 4 warps each sweeping a 33-interval chunk.
// Rank-sort knots (1 barrier), direct per-chunk state init via XOR-activity,
// warp-local reduce + emit into smem scratch, then 2-barrier compaction.
// ---------------------------------------------------------------------------
__global__ void build_kernel(const float* __restrict__ W1,
                             const float* __restrict__ b1,
                             const float* __restrict__ W2,
                             const float* __restrict__ b2,
                             const float* __restrict__ W3,
                             const float* __restrict__ b3)
{
    extern __shared__ float scr[];              // 3 * 4*CAP_W floats
    float* s_kn = scr;
    float* s_g  = scr + 4 * CAP_W;
    float* s_h  = scr + 8 * CAP_W;

    __shared__ float sa[H], sc[H], sw3[H];
    __shared__ float skey[H], sskeyv[H];
    __shared__ int   ssidx[H], spos[H];
    __shared__ unsigned char sact0[H];
    __shared__ float cby[4][H], cbg[4][H], cbh[4][H];
    __shared__ int   swcnt[4], swoff[4];

    const int s    = blockIdx.x;
    const int tid  = threadIdx.x;              // 0..127
    const int lane = tid & 31, warp = tid >> 5;
    const float t  = (float)s * (float)(1.0 / 12.0);

    if (tid == 0) {
        float elam = expf(-0.01f * t);
        float A = 100.0f * expf(-0.0196f * t);
        g_coef[s] = make_float4((float)(0.0196 / 12.0) * A * elam, A,
                                (float)(0.01 / 12.0) * elam,
                                (1.0f - expf(-0.01f * (5.0f - t))) * 100.0f);
    }

    // layer-1 unit tid: h1(spot) = relu(a*spot + c)
    float a = W1[tid];
    float c = fmaf(t, W1[H + tid], b1[tid]);
    sa[tid] = a; sc[tid] = c; sw3[tid] = W3[tid];
    const float b3v = b3[0];
    bool act0 = (c > 0.0f) || (c == 0.0f && a > 0.0f);
    sact0[tid] = act0 ? 1 : 0;

    float key = 3.0e38f;
    bool valid = false;
    if (a != 0.0f) {
        float thr = -c / a;
        if (thr > 0.0f && isfinite(thr)) { key = thr; valid = true; }
    }
    skey[tid] = key;
    const int nv = __syncthreads_count(valid);     // valid-knot count, to all threads

    // stable rank sort: rank = #{k : (key_k,k) < (key_tid,tid)}
    int rank = 0;
    #pragma unroll 4
    for (int k = 0; k < H; ++k) {
        float kk = skey[k];
        rank += (kk < key) || (kk == key && k < tid);
    }
    sskeyv[rank] = key;
    ssidx[rank]  = valid ? tid : -1;
    spos[tid]    = valid ? rank : 12345;           // never < i0 if invalid
    __syncthreads();

    // warp chunk [i0, iend) of the nv+1 intervals
    const int i0   = warp * CHUNK;
    const int iend = min(i0 + CHUNK, nv + 1);

    // direct state init at interval i0: act_k(i0) = act_k(0) XOR (pos_k < i0)
    float alpha[4], beta[4];
    #pragma unroll
    for (int q = 0; q < 4; ++q) {
        int u = lane + 32 * q;
        float al = 0.0f, be = b2[u];
        for (int k = 0; k < H; ++k) {
            bool actk = (sact0[k] != 0) ^ (spos[k] < i0);
            if (actk) {
                float w = W2[k * H + u];
                al = fmaf(sa[k], w, al);
                be = fmaf(sc[k], w, be);
            }
        }
        alpha[q] = al; beta[q] = be;
    }

    int local_n = 0;
    const int wbase = warp * CAP_W;

    for (int i = i0; i < iend; ++i) {
        if (i > i0) {                               // cross layer-1 knot i-1
            int k = ssidx[i - 1];
            float ak = sa[k];
            float sg = (ak > 0.0f) ? 1.0f : -1.0f;
            float sck = sc[k];
            #pragma unroll
            for (int q = 0; q < 4; ++q) {
                int u = lane + 32 * q;
                float w = W2[k * H + u];
                alpha[q] = fmaf(sg * ak,  w, alpha[q]);
                beta[q]  = fmaf(sg * sck, w, beta[q]);
            }
        }
        float Klo = (i == 0) ? 0.0f : sskeyv[i - 1];
        float Khi = (i < nv) ? sskeyv[i] : 3.0e38f;

        float gv = 0.0f, hv = 0.0f;
        int m = 0;
        #pragma unroll
        for (int q = 0; q < 4; ++q) {
            int u = lane + 32 * q;
            float al = alpha[q], be = beta[q];
            float pre = fmaf(al, Klo, be);
            bool act = (pre > 0.0f) || (pre == 0.0f && al > 0.0f);
            float w3v = sw3[u];
            if (act) { gv = fmaf(al, w3v, gv); hv = fmaf(be, w3v, hv); }
            // layer-2 zero crossing inside (Klo, Khi)
            float y = -be / al;
            bool cand = (al != 0.0f) && (y > Klo) && (y < Khi) && isfinite(y);
            unsigned mask = __ballot_sync(0xffffffffu, cand);
            if (cand) {
                int ofs = m + __popc(mask & ((1u << lane) - 1));
                float sg2 = (al > 0.0f) ? 1.0f : -1.0f;
                cby[warp][ofs] = y;
                cbg[warp][ofs] = sg2 * al * w3v;
                cbh[warp][ofs] = sg2 * be * w3v;
            }
            m += __popc(mask);
        }
        #pragma unroll
        for (int o = 16; o > 0; o >>= 1) {
            gv += __shfl_down_sync(0xffffffffu, gv, o);
            hv += __shfl_down_sync(0xffffffffu, hv, o);
        }
        __syncwarp();
        if (lane == 0) {
            float G = gv, Hh = hv + b3v;
            int o = wbase + local_n;
            s_kn[o] = Klo; s_g[o] = G; s_h[o] = Hh;
            ++local_n;
            for (int u2 = 1; u2 < m; ++u2) {        // insertion sort (m tiny)
                float kv = cby[warp][u2], dg = cbg[warp][u2], dh = cbh[warp][u2];
                int v = u2 - 1;
                while (v >= 0 && cby[warp][v] > kv) {
                    cby[warp][v+1] = cby[warp][v];
                    cbg[warp][v+1] = cbg[warp][v];
                    cbh[warp][v+1] = cbh[warp][v];
                    --v;
                }
                cby[warp][v+1] = kv; cbg[warp][v+1] = dg; cbh[warp][v+1] = dh;
            }
            for (int u2 = 0; u2 < m; ++u2) {
                G += cbg[warp][u2]; Hh += cbh[warp][u2];
                o = wbase + local_n;
                s_kn[o] = cby[warp][u2]; s_g[o] = G; s_h[o] = Hh;
                ++local_n;
            }
        }
        __syncwarp();
    }
    if (lane == 0) swcnt[warp] = local_n;
    __syncthreads();

    if (tid == 0) {
        int run = 0;
        for (int w = 0; w < 4; ++w) { swoff[w] = run; run += swcnt[w]; }
        g_cnt[s] = run;
    }
    __syncthreads();

    const int ntot = swoff[3] + swcnt[3];
    for (int e = tid; e < ntot; e += H) {
        int w = 3;
        if (e < swoff[1]) w = 0; else if (e < swoff[2]) w = 1; else if (e < swoff[3]) w = 2;
        int o = w * CAP_W + (e - swoff[w]);
        g_cgh[s][e] = make_float2(s_g[o], s_h[o]);
        if (e > 0) g_ckn[s][e - 1] = s_kn[o];
    }
}

// ---------------------------------------------------------------------------
// Seeds: once per step (not once per eval CTA). Same lower_bound semantics
// the eval kernel previously computed per CTA.
// ---------------------------------------------------------------------------
__global__ void seed_kernel()
{
    const int s = blockIdx.x;
    const int tid = threadIdx.x;
    const int cnt = g_cnt[s];
    __shared__ float sblo_s, sbw_s;
    if (tid == 0) {
        float lo = 0.0f, invw = 0.0f, w = 0.0f;
        if (cnt > 1) {
            lo = g_ckn[s][0];
            float hi = g_ckn[s][cnt - 2];
            if (hi > lo) { w = (hi - lo) * (1.0f / NB); invw = (float)NB / (hi - lo); }
        }
        g_brange[s] = make_float2(lo, invw);
        sblo_s = lo; sbw_s = w;
    }
    __syncthreads();
    const float* kn = g_ckn[s];
    for (int q = tid; q < NB; q += blockDim.x) {
        float left = fmaf((float)q, sbw_s, sblo_s);
        int lo = 0, hi = cnt - 1;
        while (lo < hi) {
            int mid = (lo + hi) >> 1;
            if (kn[mid] < left) lo = mid + 1; else hi = mid;
        }
        g_seed[s][q] = (unsigned short)lo;
    }
}

// ---------------------------------------------------------------------------
// Eval: grid (128 path-blocks, NCH chunks) x 512 threads. Stage tables +
// precomputed seeds into SMEM; per path-step: bucket seed + exact local scan
// + 1 fma + folded pnl update. No transcendentals in the hot loop.
// ---------------------------------------------------------------------------
__global__ void __launch_bounds__(512, 1)
eval_kernel(const float* __restrict__ spots)
{
    extern __shared__ char smem_raw[];
    float2*         sgh    = (float2*)smem_raw;                 // [SMEM_CAP]
    float*          skn    = (float*)(sgh + SMEM_CAP);          // [SMEM_CAP]
    unsigned short* sstart = (unsigned short*)(skn + SMEM_CAP); // [SPC*NB]

    __shared__ int    soff[SPC];
    __shared__ int    scnt[SPC];
    __shared__ float  sblo[SPC], sbinv[SPC];
    __shared__ float4 scoef[SPC];

    const int tid = threadIdx.x;
    const int c   = blockIdx.y;
    const int s0  = c * SPC;

    if (tid == 0) {
        int run = 0;
        for (int i = 0; i < SPC; ++i) {
            int cnt = g_cnt[s0 + i];
            scnt[i] = cnt;
            if (run + cnt <= SMEM_CAP) { soff[i] = run; run += cnt; }
            else                       { soff[i] = -1; }        // fallback: global
        }
    }
    if (tid >= 32 && tid < 32 + SPC) scoef[tid - 32] = g_coef[s0 + tid - 32];
    if (tid >= 64 && tid < 64 + SPC) {
        float2 br = g_brange[s0 + tid - 64];
        sblo[tid - 64] = br.x; sbinv[tid - 64] = br.y;
    }
    // stage precomputed seeds (SPC*NB shorts, contiguous rows)
    {
        const uint4* src = (const uint4*)(&g_seed[s0][0]);
        uint4* dst = (uint4*)sstart;
        #pragma unroll 2
        for (int v = tid; v < (SPC * NB * 2) / 16; v += 512) dst[v] = src[v];
    }
    __syncthreads();

    // stage tables
    for (int i = 0; i < SPC; ++i) {
        int off = soff[i], cnt = scnt[i];
        if (off < 0) continue;
        const float*  kn = g_ckn[s0 + i];
        const float2* gh = g_cgh[s0 + i];
        for (int q = tid; q < cnt; q += 512) {
            sgh[off + q] = gh[q];
            if (q < cnt - 1) skn[off + q] = kn[q];
        }
    }
    __syncthreads();

    const int p = blockIdx.x * 512 + tid;
    float spot = spots[s0 * BATCH_N + p];
    float pnl  = 0.0f;

    for (int i = 0; i < SPC; ++i) {
        const int s = s0 + i;
        const float spot_next = spots[(s + 1) * BATCH_N + p];
        const int cnt = scnt[i], off = soff[i];
        float2 GH;

        if (off >= 0) {
            const float* kn = skn + off;
            int b = (int)((spot - sblo[i]) * sbinv[i]);
            b = min(max(b, 0), NB - 1);
            int idx = sstart[(i << 9) + b];
            const int lim = cnt - 1;
            // exact lower_bound from any seed (bucket is only a hint)
            while (idx > 0 && kn[idx - 1] >= spot) --idx;
            while (idx < lim && kn[idx] < spot) ++idx;
            GH = sgh[off + idx];
        } else {
            const float*  kn = g_ckn[s];
            const float2* gh = g_cgh[s];
            int lo = 0, hi = cnt - 1;
            while (lo < hi) {
                int mid = (lo + hi) >> 1;
                if (kn[mid] < spot) lo = mid + 1; else hi = mid;
            }
            GH = gh[lo];
        }

        float outv = fmaf(GH.x, spot, GH.y);

        const float4 cf = scoef[i];                 // (F, A, P, D)
        float delta  = -(outv * outv) * cf.w;
        float fee    = cf.x * spot;
        float payout = cf.z * fmaxf(fmaf(-cf.y, spot, 100.0f), 0.0f);

        pnl  = pnl + (fee - payout) + delta * (spot_next - spot);
        spot = spot_next;
    }
    g_part[c][p] = pnl;
}

__global__ void reduce_kernel(float* __restrict__ out)
{
    const int p = blockIdx.x * 256 + threadIdx.x;
    out[p] = (g_part[0][p] + g_part[1][p]) + (g_part[2][p] + g_part[3][p]);
}

// ---------------------------------------------------------------------------
extern "C" void kernel_launch(void* const* d_in, const int* in_sizes, int n_in,
                              void* d_out, int out_size)
{
    const float* spots = (const float*)d_in[0];
    const float* W1    = (const float*)d_in[1];
    const float* b1    = (const float*)d_in[2];
    const float* W2    = (const float*)d_in[3];
    const float* b2    = (const float*)d_in[4];
    const float* W3    = (const float*)d_in[5];
    const float* b3    = (const float*)d_in[6];
    float*       out   = (float*)d_out;

    const int build_smem = 3 * 4 * CAP_W * (int)sizeof(float);     // ~200 KB
    cudaFuncSetAttribute(build_kernel,
                         cudaFuncAttributeMaxDynamicSharedMemorySize, build_smem);

    const int eval_smem = SMEM_CAP * 12 + SPC * NB * 2;            // ~183 KB
    cudaFuncSetAttribute(eval_kernel,
                         cudaFuncAttributeMaxDynamicSharedMemorySize, eval_smem);

    build_kernel<<<NSTEPS, H, build_smem>>>(W1, b1, W2, b2, W3, b3);
    seed_kernel<<<NSTEPS, 512>>>();
    eval_kernel<<<dim3(BATCH_N / 512, NCH), 512, eval_smem>>>(spots);
    reduce_kernel<<<BATCH_N / 256, 256>>>(out);
}